// round 12
// baseline (speedup 1.0000x reference)
#include <cuda_runtime.h>
#include <math_constants.h>

#define BATCH 16
#define LEN   128
#define VOCAB 32128
#define EMB   768
#define V4    (VOCAB / 4)   // 8032
#define E4    (EMB / 4)     // 192
#define THREADS 512
#define NW (THREADS / 32)   // 16

// Bit-exact replication of XLA f32:
//   linspace(-1,1,V)[h] = -1 + h*fl(2/(V-1));  ix = ((c+1)*V - 1)/2
//   round half-even, clip. Discrete IEEE ops (no FMA contraction).
__device__ __forceinline__ int row_from_hot(int h) {
    const float delta = 2.0f / 32127.0f;                 // compile-time, IEEE RN
    float coord = __fadd_rn(-1.0f, __fmul_rn((float)h, delta));
    float t = __fadd_rn(coord, 1.0f);
    t = __fmul_rn(t, 32128.0f);
    t = __fsub_rn(t, 1.0f);
    t = __fdiv_rn(t, 2.0f);
    float r = rintf(t);                                  // half-to-even == jnp.round
    r = fminf(fmaxf(r, 0.0f), 32127.0f);
    return (int)r;
}

__global__ void __launch_bounds__(THREADS, 4)
fused_kernel(const float* __restrict__ logits,
             const int*   __restrict__ mask,
             const int*   __restrict__ psg_ids,
             const float* __restrict__ W,
             const float* __restrict__ gumbel,
             float*       __restrict__ out)
{
    const int l   = blockIdx.x;
    const int b   = blockIdx.y;
    const int tid = threadIdx.x;
    const long tok = (long)b * LEN + l;

    __shared__ int   s_final_idx;
    __shared__ float s_wv[NW];
    __shared__ int   s_wi[NW];
    __shared__ int   s_len;

    const int m = mask[tok];   // block-uniform

    if (m != 0) {
        // ---- argmax over logits[b,l,:] + gumbel[b,l,:] (first-max tie-break) ----
        // Streaming loads: data is read exactly once -> evict-first, keep L2 clean.
        const float4* lg = reinterpret_cast<const float4*>(logits) + tok * V4;
        const float4* gn = reinterpret_cast<const float4*>(gumbel) + tok * V4;
        float best = -CUDART_INF_F;
        int   bi   = 0x7fffffff;
        #pragma unroll 4
        for (int i = tid; i < V4; i += THREADS) {
            float4 a = __ldcs(lg + i);
            float4 g = __ldcs(gn + i);
            float z0 = a.x + g.x, z1 = a.y + g.y, z2 = a.z + g.z, z3 = a.w + g.w;
            int base = i << 2;
            if (z0 > best) { best = z0; bi = base;     }
            if (z1 > best) { best = z1; bi = base + 1; }
            if (z2 > best) { best = z2; bi = base + 2; }
            if (z3 > best) { best = z3; bi = base + 3; }
        }
        // warp reduce (prefer larger value, then lower index)
        #pragma unroll
        for (int off = 16; off > 0; off >>= 1) {
            float ov = __shfl_down_sync(0xffffffffu, best, off);
            int   oi = __shfl_down_sync(0xffffffffu, bi,   off);
            if (ov > best || (ov == best && oi < bi)) { best = ov; bi = oi; }
        }
        const int wid = tid >> 5, lane = tid & 31;
        if (lane == 0) { s_wv[wid] = best; s_wi[wid] = bi; }
        __syncthreads();
        if (wid == 0) {
            best = (lane < NW) ? s_wv[lane] : -CUDART_INF_F;
            bi   = (lane < NW) ? s_wi[lane] : 0x7fffffff;
            #pragma unroll
            for (int off = 16; off > 0; off >>= 1) {
                float ov = __shfl_down_sync(0xffffffffu, best, off);
                int   oi = __shfl_down_sync(0xffffffffu, bi,   off);
                if (ov > best || (ov == best && oi < bi)) { best = ov; bi = oi; }
            }
            if (lane == 0) s_final_idx = row_from_hot(bi);
        }
    } else {
        // ---- masked-off token: need s = sum(mask[b,:]) = first zero position ----
        if (tid < LEN) {
            int mv = mask[(long)b * LEN + tid];
            int mp = (tid == 0) ? 1 : mask[(long)b * LEN + tid - 1];
            if (mv == 0 && mp != 0) s_len = tid;   // exists: mask[b,l]==0
        }
        __syncthreads();
        if (tid == 0) {
            int s = s_len;
            // l >= s here: l==s -> BOS(=1); l>s -> psg_input_ids[b, l-s-1]
            s_final_idx = (l == s) ? 1 : psg_ids[(long)b * LEN + (l - s - 1)];
        }
    }
    __syncthreads();

    // ---- out[b,l,:] = W[row,:] (bitwise copy, streaming store) ----
    const int row = s_final_idx;
    const float4* src = reinterpret_cast<const float4*>(W) + (long)row * E4;
    float4*       dst = reinterpret_cast<float4*>(out) + tok * E4;
    if (tid < E4) __stcs(dst + tid, __ldg(src + tid));
}

extern "C" void kernel_launch(void* const* d_in, const int* in_sizes, int n_in,
                              void* d_out, int out_size)
{
    const float* logits  = (const float*)d_in[0];
    const int*   mask    = (const int*)  d_in[1];
    const int*   psg_ids = (const int*)  d_in[2];
    const float* W       = (const float*)d_in[3];
    const float* gumbel  = (const float*)d_in[4];
    float*       out     = (float*)d_out;

    dim3 grid(LEN, BATCH);
    fused_kernel<<<grid, THREADS>>>(logits, mask, psg_ids, W, gumbel, out);
}

// round 13
// speedup vs baseline: 1.0257x; 1.0257x over previous
#include <cuda_runtime.h>
#include <math_constants.h>

#define BATCH 16
#define LEN   128
#define VOCAB 32128
#define EMB   768
#define V4    (VOCAB / 4)   // 8032
#define E4    (EMB / 4)     // 192
#define THREADS 512
#define NW (THREADS / 32)   // 16

// Bit-exact replication of XLA f32:
//   linspace(-1,1,V)[h] = -1 + h*fl(2/(V-1));  ix = ((c+1)*V - 1)/2
//   round half-even, clip. Discrete IEEE ops (no FMA contraction).
__device__ __forceinline__ int row_from_hot(int h) {
    const float delta = 2.0f / 32127.0f;                 // compile-time, IEEE RN
    float coord = __fadd_rn(-1.0f, __fmul_rn((float)h, delta));
    float t = __fadd_rn(coord, 1.0f);
    t = __fmul_rn(t, 32128.0f);
    t = __fsub_rn(t, 1.0f);
    t = __fdiv_rn(t, 2.0f);
    float r = rintf(t);                                  // half-to-even == jnp.round
    r = fminf(fmaxf(r, 0.0f), 32127.0f);
    return (int)r;
}

__global__ void __launch_bounds__(THREADS, 4)
fused_kernel(const float* __restrict__ logits,
             const int*   __restrict__ mask,
             const int*   __restrict__ psg_ids,
             const float* __restrict__ W,
             const float* __restrict__ gumbel,
             float*       __restrict__ out)
{
    const int l   = blockIdx.x;
    const int b   = blockIdx.y;
    const int tid = threadIdx.x;
    const long tok = (long)b * LEN + l;

    __shared__ int   s_final_idx;
    __shared__ float s_wv[NW];
    __shared__ int   s_wi[NW];
    __shared__ int   s_len;

    const int m = mask[tok];   // block-uniform

    if (m != 0) {
        // ---- argmax over logits[b,l,:] + gumbel[b,l,:] (first-max tie-break) ----
        // Streaming loads: data is read exactly once -> evict-first, keep L2 clean.
        const float4* lg = reinterpret_cast<const float4*>(logits) + tok * V4;
        const float4* gn = reinterpret_cast<const float4*>(gumbel) + tok * V4;
        float best = -CUDART_INF_F;
        int   bi   = 0x7fffffff;
        #pragma unroll 4
        for (int i = tid; i < V4; i += THREADS) {
            float4 a = __ldcs(lg + i);
            float4 g = __ldcs(gn + i);
            float z0 = a.x + g.x, z1 = a.y + g.y, z2 = a.z + g.z, z3 = a.w + g.w;
            int base = i << 2;
            if (z0 > best) { best = z0; bi = base;     }
            if (z1 > best) { best = z1; bi = base + 1; }
            if (z2 > best) { best = z2; bi = base + 2; }
            if (z3 > best) { best = z3; bi = base + 3; }
        }
        // warp reduce (prefer larger value, then lower index)
        #pragma unroll
        for (int off = 16; off > 0; off >>= 1) {
            float ov = __shfl_down_sync(0xffffffffu, best, off);
            int   oi = __shfl_down_sync(0xffffffffu, bi,   off);
            if (ov > best || (ov == best && oi < bi)) { best = ov; bi = oi; }
        }
        const int wid = tid >> 5, lane = tid & 31;
        if (lane == 0) { s_wv[wid] = best; s_wi[wid] = bi; }
        __syncthreads();
        if (wid == 0) {
            best = (lane < NW) ? s_wv[lane] : -CUDART_INF_F;
            bi   = (lane < NW) ? s_wi[lane] : 0x7fffffff;
            #pragma unroll
            for (int off = 16; off > 0; off >>= 1) {
                float ov = __shfl_down_sync(0xffffffffu, best, off);
                int   oi = __shfl_down_sync(0xffffffffu, bi,   off);
                if (ov > best || (ov == best && oi < bi)) { best = ov; bi = oi; }
            }
            if (lane == 0) s_final_idx = row_from_hot(bi);
        }
    } else {
        // ---- masked-off token: need s = sum(mask[b,:]) = first zero position ----
        if (tid < LEN) {
            int mv = mask[(long)b * LEN + tid];
            int mp = (tid == 0) ? 1 : mask[(long)b * LEN + tid - 1];
            if (mv == 0 && mp != 0) s_len = tid;   // exists: mask[b,l]==0
        }
        __syncthreads();
        if (tid == 0) {
            int s = s_len;
            // l >= s here: l==s -> BOS(=1); l>s -> psg_input_ids[b, l-s-1]
            s_final_idx = (l == s) ? 1 : psg_ids[(long)b * LEN + (l - s - 1)];
        }
    }
    __syncthreads();

    // ---- out[b,l,:] = W[row,:] (bitwise copy, streaming store) ----
    const int row = s_final_idx;
    const float4* src = reinterpret_cast<const float4*>(W) + (long)row * E4;
    float4*       dst = reinterpret_cast<float4*>(out) + tok * E4;
    if (tid < E4) __stcs(dst + tid, __ldg(src + tid));
}

extern "C" void kernel_launch(void* const* d_in, const int* in_sizes, int n_in,
                              void* d_out, int out_size)
{
    const float* logits  = (const float*)d_in[0];
    const int*   mask    = (const int*)  d_in[1];
    const int*   psg_ids = (const int*)  d_in[2];
    const float* W       = (const float*)d_in[3];
    const float* gumbel  = (const float*)d_in[4];
    float*       out     = (float*)d_out;

    dim3 grid(LEN, BATCH);
    fused_kernel<<<grid, THREADS>>>(logits, mask, psg_ids, W, gumbel, out);
}